// round 5
// baseline (speedup 1.0000x reference)
#include <cuda_runtime.h>
#include <cuda_bf16.h>

// Problem: B=8, C=256, H=W=256.
//   h      = LeakyReLU(semantic @ W1^T + b1, 0.1)
//   logits = h @ W2^T + b2
//   w      = softmax(logits, axis=1)
//   out    = x * (1 + w[b,c])
//
// Strategy: one fused gate kernel (8 blocks) + PDL-overlapped streaming scale.

#define B_DIM 8
#define C_DIM 256
#define HW4 16384         // (256*256)/4 float4s per (b,c) plane
#define V_PER_THREAD 4
#define SCALE_THREADS 256

__device__ float g_gate[B_DIM * C_DIM];    // 1 + softmax weight

// ---------------------------------------------------------------------------
// Fused gate: both MLP layers (warp-per-row, coalesced W reads) + softmax.
// Grid: B_DIM blocks, 256 threads = 8 warps; each warp owns 32 output rows.
// ---------------------------------------------------------------------------
__global__ __launch_bounds__(C_DIM) void gate_kernel(
    const float* __restrict__ semantic,
    const float* __restrict__ W1,
    const float* __restrict__ b1,
    const float* __restrict__ W2,
    const float* __restrict__ b2)
{
    const int b    = blockIdx.x;
    const int tid  = threadIdx.x;
    const int warp = tid >> 5;
    const int lane = tid & 31;

    __shared__ float s_in[C_DIM];     // layer input; reused as logits store
    __shared__ float s_h[C_DIM];      // hidden activations
    __shared__ float s_red[C_DIM];    // softmax reduction

    s_in[tid] = semantic[b * C_DIM + tid];
    __syncthreads();

    // Layer 1: h[t] = LeakyReLU(dot(s_in, W1[t,:]) + b1[t]); warp owns rows warp*32..+31
    #pragma unroll 4
    for (int r = 0; r < 32; ++r) {
        const int t = warp * 32 + r;
        const float* wrow = W1 + t * C_DIM;
        float acc = 0.0f;
        #pragma unroll
        for (int i = 0; i < C_DIM / 32; ++i) {
            const int k = lane + i * 32;
            acc = fmaf(s_in[k], wrow[k], acc);
        }
        #pragma unroll
        for (int s = 16; s > 0; s >>= 1)
            acc += __shfl_xor_sync(0xFFFFFFFFu, acc, s);
        if (lane == 0) {
            acc += b1[t];
            s_h[t] = (acc > 0.0f) ? acc : 0.1f * acc;
        }
    }
    __syncthreads();

    // Layer 2: logits[t] = dot(s_h, W2[t,:]) + b2[t]  (stored into s_in)
    #pragma unroll 4
    for (int r = 0; r < 32; ++r) {
        const int t = warp * 32 + r;
        const float* wrow = W2 + t * C_DIM;
        float acc = 0.0f;
        #pragma unroll
        for (int i = 0; i < C_DIM / 32; ++i) {
            const int k = lane + i * 32;
            acc = fmaf(s_h[k], wrow[k], acc);
        }
        #pragma unroll
        for (int s = 16; s > 0; s >>= 1)
            acc += __shfl_xor_sync(0xFFFFFFFFu, acc, s);
        if (lane == 0)
            s_in[t] = acc + b2[t];
    }
    __syncthreads();

    // Softmax over the 256 logits
    const float l = s_in[tid];
    s_red[tid] = l;
    __syncthreads();
    #pragma unroll
    for (int s = C_DIM / 2; s > 0; s >>= 1) {
        if (tid < s) s_red[tid] = fmaxf(s_red[tid], s_red[tid + s]);
        __syncthreads();
    }
    const float m = s_red[0];
    __syncthreads();

    const float e = expf(l - m);
    s_red[tid] = e;
    __syncthreads();
    #pragma unroll
    for (int s = C_DIM / 2; s > 0; s >>= 1) {
        if (tid < s) s_red[tid] += s_red[tid + s];
        __syncthreads();
    }

    g_gate[b * C_DIM + tid] = 1.0f + e / s_red[0];
}

// ---------------------------------------------------------------------------
// Streaming scale with PDL: load x BEFORE the grid-dependency sync so the
// reads overlap the gate kernel; consume the gate only after the sync.
// ---------------------------------------------------------------------------
__global__ __launch_bounds__(SCALE_THREADS) void scale_kernel(
    const float4* __restrict__ x,
    float4* __restrict__ out)
{
    const int bc = blockIdx.y;
    const long long base = (long long)bc * HW4
                         + (long long)blockIdx.x * (SCALE_THREADS * V_PER_THREAD)
                         + threadIdx.x;

    float4 v[V_PER_THREAD];
    #pragma unroll
    for (int i = 0; i < V_PER_THREAD; ++i)
        v[i] = __ldcs(&x[base + i * SCALE_THREADS]);   // evict-first, independent of gate

#if __CUDA_ARCH__ >= 900
    cudaGridDependencySynchronize();                    // wait for gate_kernel
#endif
    const float g = g_gate[bc];

    #pragma unroll
    for (int i = 0; i < V_PER_THREAD; ++i) {
        v[i].x *= g; v[i].y *= g; v[i].z *= g; v[i].w *= g;
    }

    #pragma unroll
    for (int i = 0; i < V_PER_THREAD; ++i)
        __stcs(&out[base + i * SCALE_THREADS], v[i]);
}

extern "C" void kernel_launch(void* const* d_in, const int* in_sizes, int n_in,
                              void* d_out, int out_size)
{
    const float* x        = (const float*)d_in[0];
    const float* semantic = (const float*)d_in[1];
    const float* W1       = (const float*)d_in[2];
    const float* b1       = (const float*)d_in[3];
    const float* W2       = (const float*)d_in[4];
    const float* b2       = (const float*)d_in[5];
    float* out = (float*)d_out;

    gate_kernel<<<B_DIM, C_DIM>>>(semantic, W1, b1, W2, b2);

    // Scale kernel launched with programmatic stream serialization: its
    // pre-sync load phase overlaps the gate kernel's execution.
    cudaLaunchAttribute attr[1];
    attr[0].id = cudaLaunchAttributeProgrammaticStreamSerialization;
    attr[0].val.programmaticStreamSerializationAllowed = 1;

    cudaLaunchConfig_t cfg = {};
    cfg.gridDim  = dim3(HW4 / (SCALE_THREADS * V_PER_THREAD), B_DIM * C_DIM, 1);
    cfg.blockDim = dim3(SCALE_THREADS, 1, 1);
    cfg.dynamicSmemBytes = 0;
    cfg.stream = 0;
    cfg.attrs = attr;
    cfg.numAttrs = 1;

    cudaLaunchKernelEx(&cfg, scale_kernel, (const float4*)x, (float4*)out);
}

// round 6
// speedup vs baseline: 1.1315x; 1.1315x over previous
#include <cuda_runtime.h>
#include <cuda_bf16.h>

// Problem: B=8, C=256, H=W=256.
//   h      = LeakyReLU(semantic @ W1^T + b1, 0.1)
//   logits = h @ W2^T + b2
//   w      = softmax(logits, axis=1)
//   out    = x * (1 + w[b,c])
//
// Structure: ONE fused gate kernel (8 blocks x 1024 threads) + streaming scale
// (measured 149us @ 86% DRAM = the ceiling). No PDL: measured to serialize here.

#define B_DIM 8
#define C_DIM 256
#define HW4 16384         // (256*256)/4 float4s per (b,c) plane
#define V_PER_THREAD 4
#define SCALE_THREADS 256
#define GATE_THREADS 1024
#define ROWS_PER_WARP 8   // 256 rows / 32 warps

__device__ float g_gate[B_DIM * C_DIM];    // 1 + softmax weight

// ---------------------------------------------------------------------------
// Fused gate: layer1 -> layer2 -> softmax in one kernel.
// 8 blocks (one per batch) x 1024 threads (32 warps). Each warp computes 8
// output rows per layer with 8 interleaved accumulators (MLP=8), coalesced
// 128B weight reads, shfl butterfly reduces.
// ---------------------------------------------------------------------------
__global__ __launch_bounds__(GATE_THREADS) void gate_kernel(
    const float* __restrict__ semantic,
    const float* __restrict__ W1,
    const float* __restrict__ b1,
    const float* __restrict__ W2,
    const float* __restrict__ b2)
{
    const int b    = blockIdx.x;
    const int tid  = threadIdx.x;
    const int warp = tid >> 5;
    const int lane = tid & 31;

    __shared__ float s_in[C_DIM];     // layer input
    __shared__ float s_h[C_DIM];      // hidden activations / logits
    __shared__ float s_red[C_DIM];    // softmax reduction

    if (tid < C_DIM) s_in[tid] = semantic[b * C_DIM + tid];
    __syncthreads();

    // ---- Layer 1: warp owns rows warp*8 .. warp*8+7, interleaved accs ----
    {
        const int row0 = warp * ROWS_PER_WARP;
        float acc[ROWS_PER_WARP];
        #pragma unroll
        for (int r = 0; r < ROWS_PER_WARP; ++r) acc[r] = 0.0f;

        #pragma unroll
        for (int i = 0; i < C_DIM / 32; ++i) {
            const int k = lane + i * 32;
            const float xin = s_in[k];
            #pragma unroll
            for (int r = 0; r < ROWS_PER_WARP; ++r)
                acc[r] = fmaf(xin, W1[(row0 + r) * C_DIM + k], acc[r]);
        }
        #pragma unroll
        for (int r = 0; r < ROWS_PER_WARP; ++r) {
            float a = acc[r];
            #pragma unroll
            for (int s = 16; s > 0; s >>= 1)
                a += __shfl_xor_sync(0xFFFFFFFFu, a, s);
            if (lane == 0) {
                a += b1[row0 + r];
                s_h[row0 + r] = (a > 0.0f) ? a : 0.1f * a;
            }
        }
    }
    __syncthreads();

    // ---- Layer 2: logits into s_in ----
    {
        const int row0 = warp * ROWS_PER_WARP;
        float acc[ROWS_PER_WARP];
        #pragma unroll
        for (int r = 0; r < ROWS_PER_WARP; ++r) acc[r] = 0.0f;

        #pragma unroll
        for (int i = 0; i < C_DIM / 32; ++i) {
            const int k = lane + i * 32;
            const float hin = s_h[k];
            #pragma unroll
            for (int r = 0; r < ROWS_PER_WARP; ++r)
                acc[r] = fmaf(hin, W2[(row0 + r) * C_DIM + k], acc[r]);
        }
        #pragma unroll
        for (int r = 0; r < ROWS_PER_WARP; ++r) {
            float a = acc[r];
            #pragma unroll
            for (int s = 16; s > 0; s >>= 1)
                a += __shfl_xor_sync(0xFFFFFFFFu, a, s);
            if (lane == 0)
                s_in[row0 + r] = a + b2[row0 + r];
        }
    }
    __syncthreads();

    // ---- Softmax over 256 logits (threads 0..255 active, all sync) ----
    float l = 0.0f;
    if (tid < C_DIM) {
        l = s_in[tid];
        s_red[tid] = l;
    }
    __syncthreads();
    #pragma unroll
    for (int s = C_DIM / 2; s > 0; s >>= 1) {
        if (tid < s) s_red[tid] = fmaxf(s_red[tid], s_red[tid + s]);
        __syncthreads();
    }
    const float m = s_red[0];
    __syncthreads();

    float e = 0.0f;
    if (tid < C_DIM) {
        e = expf(l - m);
        s_red[tid] = e;
    }
    __syncthreads();
    #pragma unroll
    for (int s = C_DIM / 2; s > 0; s >>= 1) {
        if (tid < s) s_red[tid] += s_red[tid + s];
        __syncthreads();
    }

    if (tid < C_DIM)
        g_gate[b * C_DIM + tid] = 1.0f + e / s_red[0];
}

// ---------------------------------------------------------------------------
// Streaming scale: out = x * gate[bc]. Measured 149us @ 86% DRAM — keep as-is.
// ---------------------------------------------------------------------------
__global__ __launch_bounds__(SCALE_THREADS) void scale_kernel(
    const float4* __restrict__ x,
    float4* __restrict__ out)
{
    const int bc = blockIdx.y;
    const float g = g_gate[bc];
    const long long base = (long long)bc * HW4
                         + (long long)blockIdx.x * (SCALE_THREADS * V_PER_THREAD)
                         + threadIdx.x;

    float4 v[V_PER_THREAD];
    #pragma unroll
    for (int i = 0; i < V_PER_THREAD; ++i)
        v[i] = x[base + i * SCALE_THREADS];

    #pragma unroll
    for (int i = 0; i < V_PER_THREAD; ++i) {
        v[i].x *= g; v[i].y *= g; v[i].z *= g; v[i].w *= g;
    }

    #pragma unroll
    for (int i = 0; i < V_PER_THREAD; ++i)
        out[base + i * SCALE_THREADS] = v[i];
}

extern "C" void kernel_launch(void* const* d_in, const int* in_sizes, int n_in,
                              void* d_out, int out_size)
{
    const float* x        = (const float*)d_in[0];
    const float* semantic = (const float*)d_in[1];
    const float* W1       = (const float*)d_in[2];
    const float* b1       = (const float*)d_in[3];
    const float* W2       = (const float*)d_in[4];
    const float* b2       = (const float*)d_in[5];
    float* out = (float*)d_out;

    gate_kernel<<<B_DIM, GATE_THREADS>>>(semantic, W1, b1, W2, b2);

    dim3 grid(HW4 / (SCALE_THREADS * V_PER_THREAD), B_DIM * C_DIM);
    scale_kernel<<<grid, SCALE_THREADS>>>((const float4*)x, (float4*)out);
}

// round 8
// speedup vs baseline: 1.1457x; 1.0125x over previous
#include <cuda_runtime.h>
#include <cuda_bf16.h>

// Problem: B=8, C=256, H=W=256.
//   h      = LeakyReLU(semantic @ W1^T + b1, 0.1)
//   logits = h @ W2^T + b2
//   w      = softmax(logits, axis=1)
//   out    = x * (1 + w[b,c])
//
// Structure (best-of-measured hybrid):
//   1) dense1: wide warp-per-row layer (256 blocks)           [R3-proven]
//   2) dense2 + softmax fused: 8 blocks x 1024 threads        [R6 layer2 code]
//   3) streaming scale: 148.8us @ 86.5% DRAM                  [frozen]

#define B_DIM 8
#define C_DIM 256
#define HW4 16384         // (256*256)/4 float4s per (b,c) plane
#define V_PER_THREAD 4
#define SCALE_THREADS 256
#define L2_THREADS 1024
#define L2_ROWS_PER_WARP 8   // 256 rows / 32 warps

__device__ float g_h[B_DIM * C_DIM];       // hidden activations
__device__ float g_gate[B_DIM * C_DIM];    // 1 + softmax weight

// ---------------------------------------------------------------------------
// Layer 1: warp-per-output-row, coalesced W1 reads. Grid (C/8, B), 256 thr.
// ---------------------------------------------------------------------------
__global__ __launch_bounds__(256) void dense1_kernel(
    const float* __restrict__ semantic,
    const float* __restrict__ W1,
    const float* __restrict__ b1,
    float* __restrict__ out)          // g_h
{
    const int b    = blockIdx.y;
    const int warp = threadIdx.x >> 5;
    const int lane = threadIdx.x & 31;
    const int t    = blockIdx.x * 8 + warp;

    __shared__ float s_in[C_DIM];
    s_in[threadIdx.x] = semantic[b * C_DIM + threadIdx.x];
    __syncthreads();

    const float* wrow = W1 + t * C_DIM;
    float acc = 0.0f;
    #pragma unroll
    for (int i = 0; i < C_DIM / 32; ++i) {
        const int k = lane + i * 32;
        acc = fmaf(s_in[k], wrow[k], acc);
    }
    #pragma unroll
    for (int s = 16; s > 0; s >>= 1)
        acc += __shfl_xor_sync(0xFFFFFFFFu, acc, s);

    if (lane == 0) {
        acc += b1[t];
        out[b * C_DIM + t] = (acc > 0.0f) ? acc : 0.1f * acc;   // LeakyReLU(0.1)
    }
}

// ---------------------------------------------------------------------------
// Layer 2 + softmax fused. Grid: B_DIM blocks x 1024 threads (32 warps).
// Each warp computes 8 logit rows with interleaved accumulators, then an
// in-block softmax produces gate = 1 + softmax(logits).
// ---------------------------------------------------------------------------
__global__ __launch_bounds__(L2_THREADS) void dense2_softmax_kernel(
    const float* __restrict__ W2,
    const float* __restrict__ b2)
{
    const int b    = blockIdx.x;
    const int tid  = threadIdx.x;
    const int warp = tid >> 5;
    const int lane = tid & 31;

    __shared__ float s_h[C_DIM];      // hidden input
    __shared__ float s_l[C_DIM];      // logits
    __shared__ float s_red[C_DIM];    // softmax reduction

    if (tid < C_DIM) s_h[tid] = g_h[b * C_DIM + tid];
    __syncthreads();

    {
        const int row0 = warp * L2_ROWS_PER_WARP;
        float acc[L2_ROWS_PER_WARP];
        #pragma unroll
        for (int r = 0; r < L2_ROWS_PER_WARP; ++r) acc[r] = 0.0f;

        #pragma unroll
        for (int i = 0; i < C_DIM / 32; ++i) {
            const int k = lane + i * 32;
            const float hin = s_h[k];
            #pragma unroll
            for (int r = 0; r < L2_ROWS_PER_WARP; ++r)
                acc[r] = fmaf(hin, W2[(row0 + r) * C_DIM + k], acc[r]);
        }
        #pragma unroll
        for (int r = 0; r < L2_ROWS_PER_WARP; ++r) {
            float a = acc[r];
            #pragma unroll
            for (int s = 16; s > 0; s >>= 1)
                a += __shfl_xor_sync(0xFFFFFFFFu, a, s);
            if (lane == 0)
                s_l[row0 + r] = a + b2[row0 + r];
        }
    }
    __syncthreads();

    // Softmax over 256 logits (threads 0..255 carry values; all threads sync)
    float l = 0.0f;
    if (tid < C_DIM) {
        l = s_l[tid];
        s_red[tid] = l;
    }
    __syncthreads();
    #pragma unroll
    for (int s = C_DIM / 2; s > 0; s >>= 1) {
        if (tid < s) s_red[tid] = fmaxf(s_red[tid], s_red[tid + s]);
        __syncthreads();
    }
    const float m = s_red[0];
    __syncthreads();

    float e = 0.0f;
    if (tid < C_DIM) {
        e = expf(l - m);
        s_red[tid] = e;
    }
    __syncthreads();
    #pragma unroll
    for (int s = C_DIM / 2; s > 0; s >>= 1) {
        if (tid < s) s_red[tid] += s_red[tid + s];
        __syncthreads();
    }

    if (tid < C_DIM)
        g_gate[b * C_DIM + tid] = 1.0f + e / s_red[0];
}

// ---------------------------------------------------------------------------
// Streaming scale: out = x * gate[bc]. Measured 148.8us @ 86.5% DRAM — frozen.
// ---------------------------------------------------------------------------
__global__ __launch_bounds__(SCALE_THREADS) void scale_kernel(
    const float4* __restrict__ x,
    float4* __restrict__ out)
{
    const int bc = blockIdx.y;
    const float g = g_gate[bc];
    const long long base = (long long)bc * HW4
                         + (long long)blockIdx.x * (SCALE_THREADS * V_PER_THREAD)
                         + threadIdx.x;

    float4 v[V_PER_THREAD];
    #pragma unroll
    for (int i = 0; i < V_PER_THREAD; ++i)
        v[i] = x[base + i * SCALE_THREADS];

    #pragma unroll
    for (int i = 0; i < V_PER_THREAD; ++i) {
        v[i].x *= g; v[i].y *= g; v[i].z *= g; v[i].w *= g;
    }

    #pragma unroll
    for (int i = 0; i < V_PER_THREAD; ++i)
        out[base + i * SCALE_THREADS] = v[i];
}

extern "C" void kernel_launch(void* const* d_in, const int* in_sizes, int n_in,
                              void* d_out, int out_size)
{
    const float* x        = (const float*)d_in[0];
    const float* semantic = (const float*)d_in[1];
    const float* W1       = (const float*)d_in[2];
    const float* b1       = (const float*)d_in[3];
    const float* W2       = (const float*)d_in[4];
    const float* b2       = (const float*)d_in[5];
    float* out = (float*)d_out;

    float* d_h; cudaGetSymbolAddress((void**)&d_h, g_h);

    dim3 l1_grid(C_DIM / 8, B_DIM);
    dense1_kernel<<<l1_grid, 256>>>(semantic, W1, b1, d_h);
    dense2_softmax_kernel<<<B_DIM, L2_THREADS>>>(W2, b2);

    dim3 grid(HW4 / (SCALE_THREADS * V_PER_THREAD), B_DIM * C_DIM);
    scale_kernel<<<grid, SCALE_THREADS>>>((const float4*)x, (float4*)out);
}

// round 9
// speedup vs baseline: 1.1607x; 1.0131x over previous
#include <cuda_runtime.h>
#include <cuda_bf16.h>

// Problem: B=8, C=256, H=W=256.
//   h      = LeakyReLU(semantic @ W1^T + b1, 0.1)
//   logits = h @ W2^T + b2
//   w      = softmax(logits, axis=1)
//   out    = x * (1 + w[b,c])
//
// Structure:
//   1) ONE cluster gate kernel: 8 clusters (one per batch) x 8 CTAs x 256 thr.
//      Both layers run at full width (64 SMs); layer boundary + softmax are
//      cluster.sync's (~0.6us) instead of kernel launches (~4us each).
//   2) streaming scale: measured 148.8-150us @ 86% DRAM — frozen.

#define B_DIM 8
#define C_DIM 256
#define HW4 16384         // (256*256)/4 float4s per (b,c) plane
#define V_PER_THREAD 4
#define SCALE_THREADS 256
#define CLUSTER_CTAS 8
#define ROWS_PER_CTA 32   // 256 / 8
#define ROWS_PER_WARP 4   // 32 rows / 8 warps

__device__ float g_h[B_DIM * C_DIM];       // hidden activations (cluster exchange)
__device__ float g_logits[B_DIM * C_DIM];  // logits (cluster exchange)
__device__ float g_gate[B_DIM * C_DIM];    // 1 + softmax weight

// ---------------------------------------------------------------------------
// Cluster gate kernel. blockIdx.x = b*8 + rank. Each CTA owns 32 output rows
// per layer; h and logits are exchanged through global memory, made coherent
// by __threadfence + barrier.cluster (which flushes L1D on sm_103a).
// ---------------------------------------------------------------------------
__global__ __launch_bounds__(C_DIM) __cluster_dims__(CLUSTER_CTAS, 1, 1)
void gate_cluster_kernel(
    const float* __restrict__ semantic,
    const float* __restrict__ W1,
    const float* __restrict__ b1,
    const float* __restrict__ W2,
    const float* __restrict__ b2)
{
    const int b    = blockIdx.x >> 3;
    const int rank = blockIdx.x & 7;
    const int tid  = threadIdx.x;
    const int warp = tid >> 5;
    const int lane = tid & 31;
    const int row0 = rank * ROWS_PER_CTA + warp * ROWS_PER_WARP;

    __shared__ float s_vec[C_DIM];    // layer input vector
    __shared__ float s_red[C_DIM];    // softmax reduction

    // ---- Layer 1: rows row0..row0+3, coalesced W1 reads, 4 interleaved accs
    s_vec[tid] = semantic[b * C_DIM + tid];
    __syncthreads();
    {
        float acc[ROWS_PER_WARP] = {0.f, 0.f, 0.f, 0.f};
        #pragma unroll
        for (int i = 0; i < C_DIM / 32; ++i) {
            const int k = lane + i * 32;
            const float xin = s_vec[k];
            #pragma unroll
            for (int r = 0; r < ROWS_PER_WARP; ++r)
                acc[r] = fmaf(xin, W1[(row0 + r) * C_DIM + k], acc[r]);
        }
        #pragma unroll
        for (int r = 0; r < ROWS_PER_WARP; ++r) {
            float a = acc[r];
            #pragma unroll
            for (int s = 16; s > 0; s >>= 1)
                a += __shfl_xor_sync(0xFFFFFFFFu, a, s);
            if (lane == 0) {
                a += b1[row0 + r];
                g_h[b * C_DIM + row0 + r] = (a > 0.0f) ? a : 0.1f * a;
            }
        }
    }
    __threadfence();
    asm volatile("barrier.cluster.arrive.aligned;" ::: "memory");
    asm volatile("barrier.cluster.wait.aligned;" ::: "memory");

    // ---- Layer 2: gather full h, compute 4 logit rows
    s_vec[tid] = g_h[b * C_DIM + tid];
    __syncthreads();
    {
        float acc[ROWS_PER_WARP] = {0.f, 0.f, 0.f, 0.f};
        #pragma unroll
        for (int i = 0; i < C_DIM / 32; ++i) {
            const int k = lane + i * 32;
            const float hin = s_vec[k];
            #pragma unroll
            for (int r = 0; r < ROWS_PER_WARP; ++r)
                acc[r] = fmaf(hin, W2[(row0 + r) * C_DIM + k], acc[r]);
        }
        #pragma unroll
        for (int r = 0; r < ROWS_PER_WARP; ++r) {
            float a = acc[r];
            #pragma unroll
            for (int s = 16; s > 0; s >>= 1)
                a += __shfl_xor_sync(0xFFFFFFFFu, a, s);
            if (lane == 0)
                g_logits[b * C_DIM + row0 + r] = a + b2[row0 + r];
        }
    }
    __threadfence();
    asm volatile("barrier.cluster.arrive.aligned;" ::: "memory");
    asm volatile("barrier.cluster.wait.aligned;" ::: "memory");

    // ---- Softmax over 256 logits (each CTA computes redundantly; each CTA
    //      writes only its own 32 channels)
    const float l = g_logits[b * C_DIM + tid];
    s_red[tid] = l;
    __syncthreads();
    #pragma unroll
    for (int s = C_DIM / 2; s > 0; s >>= 1) {
        if (tid < s) s_red[tid] = fmaxf(s_red[tid], s_red[tid + s]);
        __syncthreads();
    }
    const float m = s_red[0];
    __syncthreads();

    const float e = expf(l - m);
    s_red[tid] = e;
    __syncthreads();
    #pragma unroll
    for (int s = C_DIM / 2; s > 0; s >>= 1) {
        if (tid < s) s_red[tid] += s_red[tid + s];
        __syncthreads();
    }

    if ((tid >> 5) == rank)   // threads covering channels rank*32..rank*32+31
        g_gate[b * C_DIM + tid] = 1.0f + e / s_red[0];
}

// ---------------------------------------------------------------------------
// Streaming scale: out = x * gate[bc]. Measured 86% DRAM — frozen.
// ---------------------------------------------------------------------------
__global__ __launch_bounds__(SCALE_THREADS) void scale_kernel(
    const float4* __restrict__ x,
    float4* __restrict__ out)
{
    const int bc = blockIdx.y;
    const float g = g_gate[bc];
    const long long base = (long long)bc * HW4
                         + (long long)blockIdx.x * (SCALE_THREADS * V_PER_THREAD)
                         + threadIdx.x;

    float4 v[V_PER_THREAD];
    #pragma unroll
    for (int i = 0; i < V_PER_THREAD; ++i)
        v[i] = x[base + i * SCALE_THREADS];

    #pragma unroll
    for (int i = 0; i < V_PER_THREAD; ++i) {
        v[i].x *= g; v[i].y *= g; v[i].z *= g; v[i].w *= g;
    }

    #pragma unroll
    for (int i = 0; i < V_PER_THREAD; ++i)
        out[base + i * SCALE_THREADS] = v[i];
}

extern "C" void kernel_launch(void* const* d_in, const int* in_sizes, int n_in,
                              void* d_out, int out_size)
{
    const float* x        = (const float*)d_in[0];
    const float* semantic = (const float*)d_in[1];
    const float* W1       = (const float*)d_in[2];
    const float* b1       = (const float*)d_in[3];
    const float* W2       = (const float*)d_in[4];
    const float* b2       = (const float*)d_in[5];
    float* out = (float*)d_out;

    gate_cluster_kernel<<<B_DIM * CLUSTER_CTAS, C_DIM>>>(semantic, W1, b1, W2, b2);

    dim3 grid(HW4 / (SCALE_THREADS * V_PER_THREAD), B_DIM * C_DIM);
    scale_kernel<<<grid, SCALE_THREADS>>>((const float4*)x, (float4*)out);
}